// round 16
// baseline (speedup 1.0000x reference)
#include <cuda_runtime.h>
#include <cuda_bf16.h>
#include <math.h>
#include <stdint.h>

#define NCLS 19
#define MCOMP 5
#define KCOMP 95
#define AF 64
#define LOG2PI_F 1.8378770664093453f
#define HF 256
#define WF 256
#define TPB 640           // 20 warps, 1 CTA/SM
#define NWARP 20
#define NPASS 5           // class-group passes (4 classes per pass, quad-lane mapped)
#define ROWA 144          // A smem row: 64 bf16 (x_hat only) + 8 pad
#define ROWB 272          // B1 smem row: 128 bf16 + 8 pad
#define ROWB2 144         // B2 smem row: 64 bf16 + 8 pad
#define WREG (32 * ROWA)  // per-warp A region = 4608 B
#define NB1 120           // maha cols: 5 passes x 24
#define NB2 120           // l/mt cols: 5 passes x 24

typedef uint32_t u32;

// ---------------- device scratch (no allocs allowed) ----------------
__device__ float g_CKp[KCOMP];
__device__ float g_LDR[NCLS];
__device__ __nv_bfloat16 g_B1[NB1 * 128];   // maha: [ql | -0.5q], K=128
__device__ __nv_bfloat16 g_B2[NB2 * 64];    // l m0..4, mt, K=64
__device__ float g_blockCe[8192];
__device__ int   g_blockCnt[8192];
__device__ unsigned int g_done;
__device__ unsigned int g_chunk;

// ---------------- smem layout (bytes) ----------------
#define A_OFF    0                    // 20 x 4608 = 92160
#define B1_OFF   92160                // 120 x 272 = 32640
#define B2_OFF   124800               // 120 x 144 = 17280
#define CKP_OFF  142080               // 96 floats
#define LDR_OFF  142464               // 24 floats
#define SMEM_TOTAL 142560

// ---------------- PTX helpers ----------------
__device__ __forceinline__ u32 smem_u32(const void* p) {
    u32 a;
    asm("{ .reg .u64 t; cvta.to.shared.u64 t, %1; cvt.u32.u64 %0, t; }"
        : "=r"(a) : "l"(p));
    return a;
}
#define LDMX4(r, a) \
    asm volatile("ldmatrix.sync.aligned.m8n8.x4.shared.b16 {%0,%1,%2,%3}, [%4];" \
        : "=r"((r)[0]), "=r"((r)[1]), "=r"((r)[2]), "=r"((r)[3]) : "r"(a))
#define LDMX2(r0, r1, a) \
    asm volatile("ldmatrix.sync.aligned.m8n8.x2.shared.b16 {%0,%1}, [%2];" \
        : "=r"(r0), "=r"(r1) : "r"(a))
#define MMA(c, a, b0_, b1_) \
    asm volatile("mma.sync.aligned.m16n8k16.row.col.f32.bf16.bf16.f32 " \
        "{%0,%1,%2,%3}, {%4,%5,%6,%7}, {%8,%9}, {%0,%1,%2,%3};" \
        : "+f"((c)[0]), "+f"((c)[1]), "+f"((c)[2]), "+f"((c)[3]) \
        : "r"((a)[0]), "r"((a)[1]), "r"((a)[2]), "r"((a)[3]), "r"(b0_), "r"(b1_))
#define PREF_L2(p) asm volatile("prefetch.global.L2 [%0];" :: "l"(p))

// elementwise bf16x2 square of a fragment register
__device__ __forceinline__ u32 sq2(u32 v) {
    __nv_bfloat162 b = *reinterpret_cast<__nv_bfloat162*>(&v);
    b = __hmul2(b, b);
    return *reinterpret_cast<u32*>(&b);
}

// column index within a 24-col pass group for (class c, slot s in 0..5):
// pass = c>>2, quad-pos tg = c&3, n-tile = s>>1, parity = s&1
__device__ __forceinline__ int bcol(int c, int s) {
    return (c >> 2) * 24 + (s >> 1) * 8 + 2 * (c & 3) + (s & 1);
}

// ---------------- prep (fused): constants + split B matrices ---------
__global__ __launch_bounds__(64) void prep_kernel(
        const float* __restrict__ cov,
        const float* __restrict__ mean,
        const float* __restrict__ tmem,
        const float* __restrict__ ct,
        const float* __restrict__ cs) {
    __shared__ float red[64], red2[64];
    const int t = threadIdx.x;
    const int bk = blockIdx.x;
    const __nv_bfloat16 z = __float2bfloat16_rn(0.f);

    if (bk < KCOMP) {
        const int c = bk / 5, j = bk - 5 * c;
        const float s = cov[bk * AF + t];
        const float l = mean[bk * AF + t];
        const float q = 1.0f / (s * s);
        const int n1 = bcol(c, j) * 128;        // maha slot j: [ql | -0.5q]
        const int n2 = bcol(c, j) * 64;         // l slot j
        g_B1[n1 + t]      = __float2bfloat16_rn(l * q);
        g_B1[n1 + 64 + t] = __float2bfloat16_rn(-0.5f * q);
        g_B2[n2 + t]      = __float2bfloat16_rn(l);
        red [t] = logf(s);
        red2[t] = l * l * q;
        __syncthreads();
        #pragma unroll
        for (int st = 32; st > 0; st >>= 1) {
            if (t < st) { red[t] += red[t + st]; red2[t] += red2[t + st]; }
            __syncthreads();
        }
        if (t == 0)
            g_CKp[bk] = -0.5f * (AF * LOG2PI_F + 2.f * red[0] + red2[0]);
    } else if (bk < KCOMP + NCLS) {
        const int c = bk - KCOMP;
        const float* p = tmem + ((size_t)(c * AF + t)) * 100;
        float s = 0.f;
        for (int i = 0; i < 100; i++) s += p[i];
        s *= 0.01f;
        red[t] = s * s;
        __syncthreads();
        #pragma unroll
        for (int st = 32; st > 0; st >>= 1) {
            if (t < st) red[t] += red[t + st];
            __syncthreads();
        }
        const float n = fmaxf(sqrtf(red[0]), 1e-12f);
        g_B2[bcol(c, 5) * 64 + t] = __float2bfloat16_rn(s / n);   // mt slot
        const int np = bcol(c, 5) * 128;                          // B1 pad slot
        g_B1[np + t]      = z;
        g_B1[np + 64 + t] = z;
        if (t == 0) {
            float r = ct[c] / cs[c];
            if (isnan(r)) r = 0.f;
            g_LDR[c] = logf(r);
        }
    } else {
        // zero the 6 columns of the missing class 19 (pass 4, tg 3) in both
        #pragma unroll
        for (int s = 0; s < 6; s++) {
            const int n1 = bcol(19, s) * 128;
            const int n2 = bcol(19, s) * 64;
            g_B1[n1 + t]      = z;
            g_B1[n1 + 64 + t] = z;
            g_B2[n2 + t]      = z;
        }
        if (t == 0) { g_done = 0; g_chunk = 0; }
    }
}

// ---------------- main: x_hat-only A, x_hat^2 fragments in-register --
__global__ __launch_bounds__(TPB, 1) void main_kernel(
        const float* __restrict__ feat,
        const int*   __restrict__ mask,
        float* __restrict__ out,
        int nchunks) {
    extern __shared__ char smem[];
    const u32 sb = smem_u32(smem);
    float* sCKp = (float*)(smem + CKP_OFF);
    float* sLDR = (float*)(smem + LDR_OFF);

    const int tid = threadIdx.x;
    const int lane = tid & 31;
    const int w = tid >> 5;
    const int tg = lane & 3;           // quad position = class offset

    // ---- one-time: B1/B2 -> smem (padded rows), single copy
    for (int i = tid; i < NB1 * 16; i += TPB) {
        const int row = i >> 4, u = i & 15;
        *(uint4*)(smem + B1_OFF + row * ROWB + u * 16) =
            ((const uint4*)g_B1)[row * 16 + u];
    }
    for (int i = tid; i < NB2 * 8; i += TPB) {
        const int row = i >> 3, u = i & 7;
        *(uint4*)(smem + B2_OFF + row * ROWB2 + u * 16) =
            ((const uint4*)g_B2)[row * 8 + u];
    }
    if (tid < KCOMP) sCKp[tid] = g_CKp[tid];
    if (tid < NCLS)  sLDR[tid] = g_LDR[tid];
    __syncthreads();

    // ---- per-warp region (x_hat only)
    const u32 wbase = sb + A_OFF + (u32)w * WREG;
    char* wmem = smem + A_OFF + (size_t)w * WREG;

    // ---- ldmatrix lane address bases
    u32 aAddr0, aAddr1;
    {
        const int rin = (lane & 7) + ((lane >> 3) & 1) * 8;
        const int k16 = (lane >> 4) & 1;
        aAddr0 = wbase + (u32)rin * ROWA + k16 * 16;
        aAddr1 = aAddr0 + 16 * ROWA;
    }
    const int m15 = lane & 15;
    // B1 (K=128, row stride 272)
    const u32 b1A4 = sb + B1_OFF
        + (u32)((lane & 7) + ((lane >> 4) & 1) * 8) * ROWB
        + ((lane >> 3) & 1) * 16;
    const u32 b1A2 = sb + B1_OFF + (u32)(16 + (m15 & 7)) * ROWB
        + ((m15 >> 3) & 1) * 16;
    // B2 (K=64, row stride 144)
    const u32 b2A4 = sb + B2_OFF
        + (u32)((lane & 7) + ((lane >> 4) & 1) * 8) * ROWB2
        + ((lane >> 3) & 1) * 16;
    const u32 b2A2 = sb + B2_OFF + (u32)(16 + (m15 & 7)) * ROWB2
        + ((m15 >> 3) & 1) * 16;

    // ---- chunk loop (id prefetched one iteration ahead)
    unsigned int ck;
    if (lane == 0) ck = atomicAdd(&g_chunk, 1u);
    ck = __shfl_sync(0xffffffffu, ck, 0);

    while (ck < (unsigned int)nchunks) {
        const int pix = (int)ck * 32 + lane;
        const int hw = pix & 65535;
        const int b = pix >> 16;

        // ---- validity via packed bytes: non-ignore class count >= 12 in 4x4
        const int ww = pix & (WF - 1);
        const int hh = (pix >> 8) & (WF - 1);
        const int* mb = mask + ((size_t)b << 20) + (size_t)(hh << 2) * 1024 + (ww << 2);
        int valid = 0;
        {
            u32 pw[4];
            #pragma unroll
            for (int r = 0; r < 4; r++) {
                int4 v4 = *(const int4*)(mb + (size_t)r * 1024);
                pw[r] = (u32)v4.x | ((u32)v4.y << 8)
                      | ((u32)v4.z << 16) | ((u32)v4.w << 24);
            }
            // a >=12 majority must appear among the first 5 slots (pigeonhole)
            #pragma unroll
            for (int i = 0; i < 5; i++) {
                const u32 cand = (i < 4) ? ((pw[0] >> (8 * i)) & 0xffu)
                                         : (pw[1] & 0xffu);
                const u32 rep = cand * 0x01010101u;
                const int cnt = __popc(__vcmpeq4(pw[0], rep))
                              + __popc(__vcmpeq4(pw[1], rep))
                              + __popc(__vcmpeq4(pw[2], rep))
                              + __popc(__vcmpeq4(pw[3], rep));
                if (cand != 255u && cnt >= 96) valid = 1;   // 12 matches * 8 bits
            }
        }

        // ---- load feature (coalesced), fp32 norm, SIMD bf16x2 pack
        const float* fbp = feat + ((size_t)b << 22) + hw;
        __nv_bfloat162 xp2[AF / 2];
        float n0 = 0.f, n1 = 0.f, n2 = 0.f, n3 = 0.f;
        #pragma unroll
        for (int a = 0; a < AF; a += 4) {
            const float a0 = fbp[(size_t)a << 16];
            const float a1 = fbp[(size_t)(a + 1) << 16];
            const float a2 = fbp[(size_t)(a + 2) << 16];
            const float a3 = fbp[(size_t)(a + 3) << 16];
            n0 = fmaf(a0, a0, n0); n1 = fmaf(a1, a1, n1);
            n2 = fmaf(a2, a2, n2); n3 = fmaf(a3, a3, n3);
            xp2[a >> 1]       = __floats2bfloat162_rn(a0, a1);
            xp2[(a >> 1) + 1] = __floats2bfloat162_rn(a2, a3);
        }
        const float inv = 1.0f / fmaxf(sqrtf((n0 + n1) + (n2 + n3)), 1e-12f);
        const __nv_bfloat162 inv2 = __float2bfloat162_rn(inv);

        // ---- write A row lane = x_hat bf16 via HMUL2 (SIMD; 8 x STS.128)
        __syncwarp();
        {
            char* arow = wmem + (size_t)lane * ROWA;
            #pragma unroll
            for (int i = 0; i < 8; i++) {
                const __nv_bfloat162 e0 = __hmul2(xp2[4 * i],     inv2);
                const __nv_bfloat162 e1 = __hmul2(xp2[4 * i + 1], inv2);
                const __nv_bfloat162 e2 = __hmul2(xp2[4 * i + 2], inv2);
                const __nv_bfloat162 e3 = __hmul2(xp2[4 * i + 3], inv2);
                uint4 v0;
                v0.x = *(const u32*)&e0; v0.y = *(const u32*)&e1;
                v0.z = *(const u32*)&e2; v0.w = *(const u32*)&e3;
                ((uint4*)arow)[i] = v0;
            }
        }
        __syncwarp();

        // ---- resident x_hat A fragments (loaded ONCE per chunk)
        u32 as[4][8];
        #pragma unroll
        for (int ks = 0; ks < 4; ks++) {
            LDMX4(&as[ks][0], aAddr0 + ks * 32);
            LDMX4(&as[ks][4], aAddr1 + ks * 32);
        }

        // ---- grab next chunk id; L2-prefetch its feat + mask lines
        unsigned int nk;
        if (lane == 0) nk = atomicAdd(&g_chunk, 1u);
        nk = __shfl_sync(0xffffffffu, nk, 0);
        if (nk < (unsigned int)nchunks) {
            const int pixn = (int)nk * 32;
            const int hwn = pixn & 65535;
            const int bn = pixn >> 16;
            const float* fsrc = feat + ((size_t)bn << 22) + hwn;
            PREF_L2(fsrc + ((size_t)lane << 16));          // channels 0..31
            PREF_L2(fsrc + ((size_t)(lane + 32) << 16));   // channels 32..63
            const int wwn = hwn & (WF - 1), hhn = hwn >> 8;
            if (lane < 16) {
                const int* msrc = mask + ((size_t)bn << 20)
                                + (size_t)(hhn << 2) * 1024 + (wwn << 2)
                                + (size_t)(lane >> 2) * 1024 + (lane & 3) * 32;
                PREF_L2(msrc);
            }
        }

        // ---- per-row streaming state (rows: g, g+8, g+16, g+24)
        float gm[4]    = {-1e30f, -1e30f, -1e30f, -1e30f};
        float Zs[4]    = {0.f, 0.f, 0.f, 0.f};
        float bestL[4] = {-1e30f, -1e30f, -1e30f, -1e30f};
        float glab[4]  = {0.f, 0.f, 0.f, 0.f};

        // ---- 5 passes: GEMM-A (maha, ks0-3 = x_hat, ks4-7 = squares
        //      derived in-register) then GEMM-B (l/mt) reusing as[]
        #pragma unroll 1
        for (int sp = 0; sp < NPASS; sp++) {
            const int c = 4 * sp + tg;             // this lane's class
            const int cvalid = (c < NCLS);
            float mlse[4];

            // ===== GEMM-A: 24 maha cols, 8 K-steps =====
            {
                float cacc[24];
                #pragma unroll
                for (int i = 0; i < 24; i++) cacc[i] = 0.f;
                const u32 b4 = b1A4 + (u32)sp * (24 * ROWB);
                const u32 b2 = b1A2 + (u32)sp * (24 * ROWB);
                u32 br[4], d0, d1;
                LDMX4(br, b4);
                LDMX2(d0, d1, b2);
                #pragma unroll
                for (int ks = 0; ks < 8; ks++) {
                    u32 brn[4], dn0, dn1;
                    if (ks < 7) {
                        LDMX4(brn, b4 + (ks + 1) * 32);
                        LDMX2(dn0, dn1, b2 + (ks + 1) * 32);
                    }
                    u32 a0[4], a1[4];
                    if (ks < 4) {
                        #pragma unroll
                        for (int q = 0; q < 4; q++) {
                            a0[q] = as[ks][q];
                            a1[q] = as[ks][4 + q];
                        }
                    } else {
                        #pragma unroll
                        for (int q = 0; q < 4; q++) {
                            a0[q] = sq2(as[ks - 4][q]);
                            a1[q] = sq2(as[ks - 4][4 + q]);
                        }
                    }
                    MMA(cacc + 0,  a0, br[0], br[1]);
                    MMA(cacc + 4,  a1, br[0], br[1]);
                    MMA(cacc + 8,  a0, br[2], br[3]);
                    MMA(cacc + 12, a1, br[2], br[3]);
                    MMA(cacc + 16, a0, d0, d1);
                    MMA(cacc + 20, a1, d0, d1);
                    if (ks < 7) {
                        #pragma unroll
                        for (int q = 0; q < 4; q++) br[q] = brn[q];
                        d0 = dn0; d1 = dn1;
                    }
                }
                float ck0 = 0.f, ck1 = 0.f, ck2 = 0.f, ck3 = 0.f, ck4 = 0.f;
                if (cvalid) {
                    ck0 = sCKp[c * 5 + 0]; ck1 = sCKp[c * 5 + 1];
                    ck2 = sCKp[c * 5 + 2]; ck3 = sCKp[c * 5 + 3];
                    ck4 = sCKp[c * 5 + 4];
                }
                #pragma unroll
                for (int r = 0; r < 4; r++) {
                    const int o = ((r & 1) << 1) + ((r >> 1) << 2);
                    const float m0 = cacc[o]        + ck0;
                    const float m1 = cacc[o + 1]    + ck1;
                    const float m2 = cacc[8 + o]    + ck2;
                    const float m3 = cacc[8 + o + 1] + ck3;
                    const float m4 = cacc[16 + o]   + ck4;
                    float mm = fmaxf(fmaxf(fmaxf(m0, m1), fmaxf(m2, m3)), m4);
                    float ms = __expf(m0 - mm) + __expf(m1 - mm) + __expf(m2 - mm)
                             + __expf(m3 - mm) + __expf(m4 - mm);
                    mlse[r] = mm + __logf(ms);
                }
            }

            // ===== GEMM-B: 24 l/mt cols, 4 K-steps, A from registers =====
            {
                float cacc[24];
                #pragma unroll
                for (int i = 0; i < 24; i++) cacc[i] = 0.f;
                const u32 b4 = b2A4 + (u32)sp * (24 * ROWB2);
                const u32 b2 = b2A2 + (u32)sp * (24 * ROWB2);
                u32 br[4], d0, d1;
                LDMX4(br, b4);
                LDMX2(d0, d1, b2);
                #pragma unroll
                for (int ks = 0; ks < 4; ks++) {
                    u32 brn[4], dn0, dn1;
                    if (ks < 3) {
                        LDMX4(brn, b4 + (ks + 1) * 32);
                        LDMX2(dn0, dn1, b2 + (ks + 1) * 32);
                    }
                    MMA(cacc + 0,  &as[ks][0], br[0], br[1]);
                    MMA(cacc + 4,  &as[ks][4], br[0], br[1]);
                    MMA(cacc + 8,  &as[ks][0], br[2], br[3]);
                    MMA(cacc + 12, &as[ks][4], br[2], br[3]);
                    MMA(cacc + 16, &as[ks][0], d0, d1);
                    MMA(cacc + 20, &as[ks][4], d0, d1);
                    if (ks < 3) {
                        #pragma unroll
                        for (int q = 0; q < 4; q++) br[q] = brn[q];
                        d0 = dn0; d1 = dn1;
                    }
                }
                const float ldr = cvalid ? sLDR[c] : 0.f;
                #pragma unroll
                for (int r = 0; r < 4; r++) {
                    const int o = ((r & 1) << 1) + ((r >> 1) << 2);
                    float lx = fmaxf(fmaxf(fmaxf(cacc[o], cacc[o + 1]),
                                           fmaxf(cacc[8 + o], cacc[8 + o + 1])),
                                     cacc[16 + o]);
                    const float simlog = cacc[16 + o + 1];
                    const float L = ldr + simlog + mlse[r];
                    const float g = lx * 0.01f;
                    if (cvalid) {
                        if (g > gm[r]) { Zs[r] = Zs[r] * __expf(gm[r] - g) + 1.f; gm[r] = g; }
                        else           { Zs[r] += __expf(g - gm[r]); }
                        if (L > bestL[r]) { bestL[r] = L; glab[r] = g; }
                    }
                }
            }
        }

        // ---- quad combine (classes split across the 4 quad lanes)
        float ceSum = 0.f;
        int cntSum = 0;
        const int g0 = lane >> 2;
        #pragma unroll
        for (int r = 0; r < 4; r++) {
            float gmv = gm[r], Zv = Zs[r], bL = bestL[r], gl = glab[r];
            #pragma unroll
            for (int off = 1; off <= 2; off <<= 1) {
                const float og  = __shfl_xor_sync(0xffffffffu, gmv, off);
                const float oZ  = __shfl_xor_sync(0xffffffffu, Zv, off);
                const float ob  = __shfl_xor_sync(0xffffffffu, bL, off);
                const float ogl = __shfl_xor_sync(0xffffffffu, gl, off);
                const float nm = fmaxf(gmv, og);
                Zv = Zv * __expf(gmv - nm) + oZ * __expf(og - nm);
                gmv = nm;
                if (ob > bL) { bL = ob; gl = ogl; }
            }
            const int row = g0 + r * 8;
            const int vr = __shfl_sync(0xffffffffu, valid, row);
            ceSum += vr ? (gmv + __logf(Zv) - gl) : 0.f;
            cntSum += vr;
        }
        if (tg != 0) { ceSum = 0.f; cntSum = 0; }   // one contribution per pixel

        // deterministic warp butterfly reduction -> per-chunk partial
        #pragma unroll
        for (int off = 16; off > 0; off >>= 1) {
            ceSum  += __shfl_xor_sync(0xffffffffu, ceSum, off);
            cntSum += __shfl_xor_sync(0xffffffffu, cntSum, off);
        }
        if (lane == 0) {
            g_blockCe[ck]  = ceSum;
            g_blockCnt[ck] = cntSum;
        }

        ck = nk;
    }

    // ---- fused finalize: last CTA reduces all per-chunk partials
    __shared__ bool isLast;
    __shared__ float sfw[NWARP];
    __shared__ int   siw[NWARP];
    __threadfence();
    __syncthreads();
    if (tid == 0) {
        unsigned int o = atomicAdd(&g_done, 1u);
        isLast = (o == (unsigned int)(gridDim.x - 1));
    }
    __syncthreads();
    if (isLast) {
        __threadfence();
        float s = 0.f; int c = 0;
        for (int i = tid; i < nchunks; i += TPB) {
            s += g_blockCe[i];
            c += g_blockCnt[i];
        }
        #pragma unroll
        for (int off = 16; off > 0; off >>= 1) {
            s += __shfl_xor_sync(0xffffffffu, s, off);
            c += __shfl_xor_sync(0xffffffffu, c, off);
        }
        if (lane == 0) { sfw[w] = s; siw[w] = c; }
        __syncthreads();
        if (tid == 0) {
            float tot = 0.f; int cnt = 0;
            #pragma unroll
            for (int i = 0; i < NWARP; i++) { tot += sfw[i]; cnt += siw[i]; }
            out[0] = tot / fmaxf((float)cnt, 1.0f);
        }
    }
}

// ---------------- launch ----------------
extern "C" void kernel_launch(void* const* d_in, const int* in_sizes, int n_in,
                              void* d_out, int out_size) {
    const float* feat = (const float*)d_in[0];
    const int*   mask = (const int*)d_in[1];
    const float* mean = (const float*)d_in[2];
    const float* cov  = (const float*)d_in[3];
    const float* tmem = (const float*)d_in[4];
    const float* ct   = (const float*)d_in[5];
    const float* cs   = (const float*)d_in[6];

    const int B = in_sizes[0] / (AF * HF * WF);
    const int npix = B * HF * WF;
    const int nchunks = npix / 32;

    cudaFuncSetAttribute(main_kernel,
                         cudaFuncAttributeMaxDynamicSharedMemorySize, SMEM_TOTAL);

    prep_kernel<<<KCOMP + NCLS + 1, 64>>>(cov, mean, tmem, ct, cs);
    main_kernel<<<148, TPB, SMEM_TOTAL>>>(feat, mask, (float*)d_out, nchunks);
}

// round 17
// speedup vs baseline: 1.2036x; 1.2036x over previous
#include <cuda_runtime.h>
#include <cuda_bf16.h>
#include <math.h>
#include <stdint.h>

#define NCLS 19
#define MCOMP 5
#define KCOMP 95
#define AF 64
#define LOG2PI_F 1.8378770664093453f
#define HF 256
#define WF 256
#define TPB 640           // 20 warps, 1 CTA/SM
#define NWARP 20
#define NPASS 5           // class-group passes (4 classes per pass, quad-lane mapped)
#define ROWA 144          // A smem row: 64 bf16 (x_hat only) + 8 pad
#define ROWB 272          // B1 smem row: 128 bf16 + 8 pad
#define ROWB2 144         // B2 smem row: 64 bf16 + 8 pad
#define WREG (32 * ROWA)  // per-warp A region = 4608 B
#define NB1 120           // maha cols: 5 passes x 24
#define NB2 120           // l/mt cols: 5 passes x 24

typedef uint32_t u32;

// ---------------- device scratch (no allocs allowed) ----------------
__device__ float g_CKp[KCOMP];
__device__ float g_LDR[NCLS];
__device__ __nv_bfloat16 g_B1[NB1 * 128];   // maha: [ql | -0.5q], K=128
__device__ __nv_bfloat16 g_B2[NB2 * 64];    // l m0..4, mt, K=64
__device__ float g_blockCe[8192];
__device__ int   g_blockCnt[8192];
__device__ unsigned int g_done;
__device__ unsigned int g_chunk;

// ---------------- smem layout (bytes) ----------------
#define A_OFF    0                    // 20 x 4608 = 92160
#define B1_OFF   92160                // 120 x 272 = 32640
#define B2_OFF   124800               // 120 x 144 = 17280
#define CKP_OFF  142080               // 96 floats
#define LDR_OFF  142464               // 24 floats
#define SMEM_TOTAL 142560

// ---------------- PTX helpers ----------------
__device__ __forceinline__ u32 smem_u32(const void* p) {
    u32 a;
    asm("{ .reg .u64 t; cvta.to.shared.u64 t, %1; cvt.u32.u64 %0, t; }"
        : "=r"(a) : "l"(p));
    return a;
}
#define LDMX4(r, a) \
    asm volatile("ldmatrix.sync.aligned.m8n8.x4.shared.b16 {%0,%1,%2,%3}, [%4];" \
        : "=r"((r)[0]), "=r"((r)[1]), "=r"((r)[2]), "=r"((r)[3]) : "r"(a))
#define LDMX2(r0, r1, a) \
    asm volatile("ldmatrix.sync.aligned.m8n8.x2.shared.b16 {%0,%1}, [%2];" \
        : "=r"(r0), "=r"(r1) : "r"(a))
#define MMA(c, a, b0_, b1_) \
    asm volatile("mma.sync.aligned.m16n8k16.row.col.f32.bf16.bf16.f32 " \
        "{%0,%1,%2,%3}, {%4,%5,%6,%7}, {%8,%9}, {%0,%1,%2,%3};" \
        : "+f"((c)[0]), "+f"((c)[1]), "+f"((c)[2]), "+f"((c)[3]) \
        : "r"((a)[0]), "r"((a)[1]), "r"((a)[2]), "r"((a)[3]), "r"(b0_), "r"(b1_))
#define PREF_L2(p) asm volatile("prefetch.global.L2 [%0];" :: "l"(p))

// elementwise bf16x2 square of a fragment register
__device__ __forceinline__ u32 sq2(u32 v) {
    __nv_bfloat162 b = *reinterpret_cast<__nv_bfloat162*>(&v);
    b = __hmul2(b, b);
    return *reinterpret_cast<u32*>(&b);
}

// column index within a 24-col pass group for (class c, slot s in 0..5):
// pass = c>>2, quad-pos tg = c&3, n-tile = s>>1, parity = s&1
__device__ __forceinline__ int bcol(int c, int s) {
    return (c >> 2) * 24 + (s >> 1) * 8 + 2 * (c & 3) + (s & 1);
}

// ---------------- prep (fused): constants + split B matrices ---------
__global__ __launch_bounds__(64) void prep_kernel(
        const float* __restrict__ cov,
        const float* __restrict__ mean,
        const float* __restrict__ tmem,
        const float* __restrict__ ct,
        const float* __restrict__ cs) {
    __shared__ float red[64], red2[64];
    const int t = threadIdx.x;
    const int bk = blockIdx.x;
    const __nv_bfloat16 z = __float2bfloat16_rn(0.f);

    if (bk < KCOMP) {
        const int c = bk / 5, j = bk - 5 * c;
        const float s = cov[bk * AF + t];
        const float l = mean[bk * AF + t];
        const float q = 1.0f / (s * s);
        const int n1 = bcol(c, j) * 128;        // maha slot j: [ql | -0.5q]
        const int n2 = bcol(c, j) * 64;         // l slot j
        g_B1[n1 + t]      = __float2bfloat16_rn(l * q);
        g_B1[n1 + 64 + t] = __float2bfloat16_rn(-0.5f * q);
        g_B2[n2 + t]      = __float2bfloat16_rn(l);
        red [t] = logf(s);
        red2[t] = l * l * q;
        __syncthreads();
        #pragma unroll
        for (int st = 32; st > 0; st >>= 1) {
            if (t < st) { red[t] += red[t + st]; red2[t] += red2[t + st]; }
            __syncthreads();
        }
        if (t == 0)
            g_CKp[bk] = -0.5f * (AF * LOG2PI_F + 2.f * red[0] + red2[0]);
    } else if (bk < KCOMP + NCLS) {
        const int c = bk - KCOMP;
        const float* p = tmem + ((size_t)(c * AF + t)) * 100;
        float s = 0.f;
        for (int i = 0; i < 100; i++) s += p[i];
        s *= 0.01f;
        red[t] = s * s;
        __syncthreads();
        #pragma unroll
        for (int st = 32; st > 0; st >>= 1) {
            if (t < st) red[t] += red[t + st];
            __syncthreads();
        }
        const float n = fmaxf(sqrtf(red[0]), 1e-12f);
        g_B2[bcol(c, 5) * 64 + t] = __float2bfloat16_rn(s / n);   // mt slot
        const int np = bcol(c, 5) * 128;                          // B1 pad slot
        g_B1[np + t]      = z;
        g_B1[np + 64 + t] = z;
        if (t == 0) {
            float r = ct[c] / cs[c];
            if (isnan(r)) r = 0.f;
            g_LDR[c] = logf(r);
        }
    } else {
        // zero the 6 columns of the missing class 19 (pass 4, tg 3) in both
        #pragma unroll
        for (int s = 0; s < 6; s++) {
            const int n1 = bcol(19, s) * 128;
            const int n2 = bcol(19, s) * 64;
            g_B1[n1 + t]      = z;
            g_B1[n1 + 64 + t] = z;
            g_B2[n2 + t]      = z;
        }
        if (t == 0) { g_done = 0; g_chunk = 0; }
    }
}

// ---------------- main: R15 phase structure, x_hat-only A ------------
__global__ __launch_bounds__(TPB, 1) void main_kernel(
        const float* __restrict__ feat,
        const int*   __restrict__ mask,
        float* __restrict__ out,
        int nchunks) {
    extern __shared__ char smem[];
    const u32 sb = smem_u32(smem);
    float* sCKp = (float*)(smem + CKP_OFF);
    float* sLDR = (float*)(smem + LDR_OFF);

    const int tid = threadIdx.x;
    const int lane = tid & 31;
    const int w = tid >> 5;
    const int tg = lane & 3;           // quad position = class offset

    // ---- one-time: B1/B2 -> smem (padded rows), single copy
    for (int i = tid; i < NB1 * 16; i += TPB) {
        const int row = i >> 4, u = i & 15;
        *(uint4*)(smem + B1_OFF + row * ROWB + u * 16) =
            ((const uint4*)g_B1)[row * 16 + u];
    }
    for (int i = tid; i < NB2 * 8; i += TPB) {
        const int row = i >> 3, u = i & 7;
        *(uint4*)(smem + B2_OFF + row * ROWB2 + u * 16) =
            ((const uint4*)g_B2)[row * 8 + u];
    }
    if (tid < KCOMP) sCKp[tid] = g_CKp[tid];
    if (tid < NCLS)  sLDR[tid] = g_LDR[tid];
    __syncthreads();

    // ---- per-warp region (x_hat only)
    const u32 wbase = sb + A_OFF + (u32)w * WREG;
    char* wmem = smem + A_OFF + (size_t)w * WREG;

    // ---- ldmatrix lane address bases
    u32 aAddr0, aAddr1;
    {
        const int rin = (lane & 7) + ((lane >> 3) & 1) * 8;
        const int k16 = (lane >> 4) & 1;
        aAddr0 = wbase + (u32)rin * ROWA + k16 * 16;
        aAddr1 = aAddr0 + 16 * ROWA;
    }
    const int m15 = lane & 15;
    // B1 (K=128, row stride 272)
    const u32 b1A4 = sb + B1_OFF
        + (u32)((lane & 7) + ((lane >> 4) & 1) * 8) * ROWB
        + ((lane >> 3) & 1) * 16;
    const u32 b1A2 = sb + B1_OFF + (u32)(16 + (m15 & 7)) * ROWB
        + ((m15 >> 3) & 1) * 16;
    // B2 (K=64, row stride 144)
    const u32 b2A4 = sb + B2_OFF
        + (u32)((lane & 7) + ((lane >> 4) & 1) * 8) * ROWB2
        + ((lane >> 3) & 1) * 16;
    const u32 b2A2 = sb + B2_OFF + (u32)(16 + (m15 & 7)) * ROWB2
        + ((m15 >> 3) & 1) * 16;

    // ---- chunk loop (id prefetched one iteration ahead)
    unsigned int ck;
    if (lane == 0) ck = atomicAdd(&g_chunk, 1u);
    ck = __shfl_sync(0xffffffffu, ck, 0);

    while (ck < (unsigned int)nchunks) {
        const int pix = (int)ck * 32 + lane;
        const int hw = pix & 65535;
        const int b = pix >> 16;

        // ---- validity via packed bytes: non-ignore class count >= 12 in 4x4
        const int ww = pix & (WF - 1);
        const int hh = (pix >> 8) & (WF - 1);
        const int* mb = mask + ((size_t)b << 20) + (size_t)(hh << 2) * 1024 + (ww << 2);
        int valid = 0;
        {
            u32 pw[4];
            #pragma unroll
            for (int r = 0; r < 4; r++) {
                int4 v4 = *(const int4*)(mb + (size_t)r * 1024);
                pw[r] = (u32)v4.x | ((u32)v4.y << 8)
                      | ((u32)v4.z << 16) | ((u32)v4.w << 24);
            }
            // a >=12 majority must appear among the first 5 slots (pigeonhole)
            #pragma unroll
            for (int i = 0; i < 5; i++) {
                const u32 cand = (i < 4) ? ((pw[0] >> (8 * i)) & 0xffu)
                                         : (pw[1] & 0xffu);
                const u32 rep = cand * 0x01010101u;
                const int cnt = __popc(__vcmpeq4(pw[0], rep))
                              + __popc(__vcmpeq4(pw[1], rep))
                              + __popc(__vcmpeq4(pw[2], rep))
                              + __popc(__vcmpeq4(pw[3], rep));
                if (cand != 255u && cnt >= 96) valid = 1;   // 12 matches * 8 bits
            }
        }

        // ---- load feature (coalesced), fp32 norm, SIMD bf16x2 pack
        const float* fbp = feat + ((size_t)b << 22) + hw;
        __nv_bfloat162 xp2[AF / 2];
        float n0 = 0.f, n1 = 0.f, n2 = 0.f, n3 = 0.f;
        #pragma unroll
        for (int a = 0; a < AF; a += 4) {
            const float a0 = fbp[(size_t)a << 16];
            const float a1 = fbp[(size_t)(a + 1) << 16];
            const float a2 = fbp[(size_t)(a + 2) << 16];
            const float a3 = fbp[(size_t)(a + 3) << 16];
            n0 = fmaf(a0, a0, n0); n1 = fmaf(a1, a1, n1);
            n2 = fmaf(a2, a2, n2); n3 = fmaf(a3, a3, n3);
            xp2[a >> 1]       = __floats2bfloat162_rn(a0, a1);
            xp2[(a >> 1) + 1] = __floats2bfloat162_rn(a2, a3);
        }
        const float inv = 1.0f / fmaxf(sqrtf((n0 + n1) + (n2 + n3)), 1e-12f);
        const __nv_bfloat162 inv2 = __float2bfloat162_rn(inv);

        // ---- write A row lane = x_hat bf16 via HMUL2 (SIMD; 8 x STS.128)
        __syncwarp();
        {
            char* arow = wmem + (size_t)lane * ROWA;
            #pragma unroll
            for (int i = 0; i < 8; i++) {
                const __nv_bfloat162 e0 = __hmul2(xp2[4 * i],     inv2);
                const __nv_bfloat162 e1 = __hmul2(xp2[4 * i + 1], inv2);
                const __nv_bfloat162 e2 = __hmul2(xp2[4 * i + 2], inv2);
                const __nv_bfloat162 e3 = __hmul2(xp2[4 * i + 3], inv2);
                uint4 v0;
                v0.x = *(const u32*)&e0; v0.y = *(const u32*)&e1;
                v0.z = *(const u32*)&e2; v0.w = *(const u32*)&e3;
                ((uint4*)arow)[i] = v0;
            }
        }
        __syncwarp();

        // ---- grab next chunk id; L2-prefetch its feat + mask lines
        unsigned int nk;
        if (lane == 0) nk = atomicAdd(&g_chunk, 1u);
        nk = __shfl_sync(0xffffffffu, nk, 0);
        if (nk < (unsigned int)nchunks) {
            const int pixn = (int)nk * 32;
            const int hwn = pixn & 65535;
            const int bn = pixn >> 16;
            const float* fsrc = feat + ((size_t)bn << 22) + hwn;
            PREF_L2(fsrc + ((size_t)lane << 16));          // channels 0..31
            PREF_L2(fsrc + ((size_t)(lane + 32) << 16));   // channels 32..63
            const int wwn = hwn & (WF - 1), hhn = hwn >> 8;
            if (lane < 16) {
                const int* msrc = mask + ((size_t)bn << 20)
                                + (size_t)(hhn << 2) * 1024 + (wwn << 2)
                                + (size_t)(lane >> 2) * 1024 + (lane & 3) * 32;
                PREF_L2(msrc);
            }
        }

        // ---- per-row streaming state (rows: g, g+8, g+16, g+24)
        float gm[4]    = {-1e30f, -1e30f, -1e30f, -1e30f};
        float Zs[4]    = {0.f, 0.f, 0.f, 0.f};
        float bestL[4] = {-1e30f, -1e30f, -1e30f, -1e30f};
        float glab[4]  = {0.f, 0.f, 0.f, 0.f};

        // ---- 5 passes: GEMM-A (maha; ks4-7 = streamed+sq2, ks0-3 = saved)
        //      then GEMM-B (l/mt) reusing the saved x_hat fragments
        #pragma unroll 1
        for (int sp = 0; sp < NPASS; sp++) {
            const int c = 4 * sp + tg;             // this lane's class
            const int cvalid = (c < NCLS);
            float mlse[4];
            u32 as[4][8];                          // saved x_hat A fragments

            // ===== GEMM-A: 24 maha cols, 8 K-steps (4..7 then 0..3) =====
            {
                float cacc[24];
                #pragma unroll
                for (int i = 0; i < 24; i++) cacc[i] = 0.f;
                const u32 b4 = b1A4 + (u32)sp * (24 * ROWB);
                const u32 b2 = b1A2 + (u32)sp * (24 * ROWB);

                // phase 1: ks 4..7 (x_hat^2 via in-place sq2), A streamed
                {
                    u32 a0[4], a1[4], br[4], d0, d1;
                    LDMX4(a0, aAddr0);
                    LDMX4(a1, aAddr1);
                    LDMX4(br, b4 + 4 * 32);
                    LDMX2(d0, d1, b2 + 4 * 32);
                    #pragma unroll
                    for (int q = 0; q < 4; q++) { a0[q] = sq2(a0[q]); a1[q] = sq2(a1[q]); }
                    #pragma unroll
                    for (int ks = 4; ks < 8; ks++) {
                        u32 a0n[4], a1n[4], brn[4], dn0, dn1;
                        if (ks < 7) {
                            LDMX4(a0n, aAddr0 + (ks - 3) * 32);
                            LDMX4(a1n, aAddr1 + (ks - 3) * 32);
                            LDMX4(brn, b4 + (ks + 1) * 32);
                            LDMX2(dn0, dn1, b2 + (ks + 1) * 32);
                        }
                        MMA(cacc + 0,  a0, br[0], br[1]);
                        MMA(cacc + 4,  a1, br[0], br[1]);
                        MMA(cacc + 8,  a0, br[2], br[3]);
                        MMA(cacc + 12, a1, br[2], br[3]);
                        MMA(cacc + 16, a0, d0, d1);
                        MMA(cacc + 20, a1, d0, d1);
                        if (ks < 7) {
                            #pragma unroll
                            for (int q = 0; q < 4; q++) {
                                a0[q] = sq2(a0n[q]); a1[q] = sq2(a1n[q]); br[q] = brn[q];
                            }
                            d0 = dn0; d1 = dn1;
                        }
                    }
                }
                // phase 2: ks 0..3 (x_hat half), A saved for GEMM-B
                {
                    u32 br[4], d0, d1;
                    LDMX4(&as[0][0], aAddr0);
                    LDMX4(&as[0][4], aAddr1);
                    LDMX4(br, b4);
                    LDMX2(d0, d1, b2);
                    #pragma unroll
                    for (int ks = 0; ks < 4; ks++) {
                        u32 brn[4], dn0, dn1;
                        if (ks < 3) {
                            LDMX4(&as[ks + 1][0], aAddr0 + (ks + 1) * 32);
                            LDMX4(&as[ks + 1][4], aAddr1 + (ks + 1) * 32);
                            LDMX4(brn, b4 + (ks + 1) * 32);
                            LDMX2(dn0, dn1, b2 + (ks + 1) * 32);
                        }
                        MMA(cacc + 0,  &as[ks][0], br[0], br[1]);
                        MMA(cacc + 4,  &as[ks][4], br[0], br[1]);
                        MMA(cacc + 8,  &as[ks][0], br[2], br[3]);
                        MMA(cacc + 12, &as[ks][4], br[2], br[3]);
                        MMA(cacc + 16, &as[ks][0], d0, d1);
                        MMA(cacc + 20, &as[ks][4], d0, d1);
                        if (ks < 3) {
                            #pragma unroll
                            for (int q = 0; q < 4; q++) br[q] = brn[q];
                            d0 = dn0; d1 = dn1;
                        }
                    }
                }
                float ck0 = 0.f, ck1 = 0.f, ck2 = 0.f, ck3 = 0.f, ck4 = 0.f;
                if (cvalid) {
                    ck0 = sCKp[c * 5 + 0]; ck1 = sCKp[c * 5 + 1];
                    ck2 = sCKp[c * 5 + 2]; ck3 = sCKp[c * 5 + 3];
                    ck4 = sCKp[c * 5 + 4];
                }
                #pragma unroll
                for (int r = 0; r < 4; r++) {
                    const int o = ((r & 1) << 1) + ((r >> 1) << 2);
                    const float m0 = cacc[o]        + ck0;
                    const float m1 = cacc[o + 1]    + ck1;
                    const float m2 = cacc[8 + o]    + ck2;
                    const float m3 = cacc[8 + o + 1] + ck3;
                    const float m4 = cacc[16 + o]   + ck4;
                    float mm = fmaxf(fmaxf(fmaxf(m0, m1), fmaxf(m2, m3)), m4);
                    float ms = __expf(m0 - mm) + __expf(m1 - mm) + __expf(m2 - mm)
                             + __expf(m3 - mm) + __expf(m4 - mm);
                    mlse[r] = mm + __logf(ms);
                }
            }

            // ===== GEMM-B: 24 l/mt cols, 4 K-steps, A from registers =====
            {
                float cacc[24];
                #pragma unroll
                for (int i = 0; i < 24; i++) cacc[i] = 0.f;
                const u32 b4 = b2A4 + (u32)sp * (24 * ROWB2);
                const u32 b2 = b2A2 + (u32)sp * (24 * ROWB2);
                u32 br[4], d0, d1;
                LDMX4(br, b4);
                LDMX2(d0, d1, b2);
                #pragma unroll
                for (int ks = 0; ks < 4; ks++) {
                    u32 brn[4], dn0, dn1;
                    if (ks < 3) {
                        LDMX4(brn, b4 + (ks + 1) * 32);
                        LDMX2(dn0, dn1, b2 + (ks + 1) * 32);
                    }
                    MMA(cacc + 0,  &as[ks][0], br[0], br[1]);
                    MMA(cacc + 4,  &as[ks][4], br[0], br[1]);
                    MMA(cacc + 8,  &as[ks][0], br[2], br[3]);
                    MMA(cacc + 12, &as[ks][4], br[2], br[3]);
                    MMA(cacc + 16, &as[ks][0], d0, d1);
                    MMA(cacc + 20, &as[ks][4], d0, d1);
                    if (ks < 3) {
                        #pragma unroll
                        for (int q = 0; q < 4; q++) br[q] = brn[q];
                        d0 = dn0; d1 = dn1;
                    }
                }
                const float ldr = cvalid ? sLDR[c] : 0.f;
                #pragma unroll
                for (int r = 0; r < 4; r++) {
                    const int o = ((r & 1) << 1) + ((r >> 1) << 2);
                    float lx = fmaxf(fmaxf(fmaxf(cacc[o], cacc[o + 1]),
                                           fmaxf(cacc[8 + o], cacc[8 + o + 1])),
                                     cacc[16 + o]);
                    const float simlog = cacc[16 + o + 1];
                    const float L = ldr + simlog + mlse[r];
                    const float g = lx * 0.01f;
                    if (cvalid) {
                        if (g > gm[r]) { Zs[r] = Zs[r] * __expf(gm[r] - g) + 1.f; gm[r] = g; }
                        else           { Zs[r] += __expf(g - gm[r]); }
                        if (L > bestL[r]) { bestL[r] = L; glab[r] = g; }
                    }
                }
            }
        }

        // ---- quad combine (classes split across the 4 quad lanes)
        float ceSum = 0.f;
        int cntSum = 0;
        const int g0 = lane >> 2;
        #pragma unroll
        for (int r = 0; r < 4; r++) {
            float gmv = gm[r], Zv = Zs[r], bL = bestL[r], gl = glab[r];
            #pragma unroll
            for (int off = 1; off <= 2; off <<= 1) {
                const float og  = __shfl_xor_sync(0xffffffffu, gmv, off);
                const float oZ  = __shfl_xor_sync(0xffffffffu, Zv, off);
                const float ob  = __shfl_xor_sync(0xffffffffu, bL, off);
                const float ogl = __shfl_xor_sync(0xffffffffu, gl, off);
                const float nm = fmaxf(gmv, og);
                Zv = Zv * __expf(gmv - nm) + oZ * __expf(og - nm);
                gmv = nm;
                if (ob > bL) { bL = ob; gl = ogl; }
            }
            const int row = g0 + r * 8;
            const int vr = __shfl_sync(0xffffffffu, valid, row);
            ceSum += vr ? (gmv + __logf(Zv) - gl) : 0.f;
            cntSum += vr;
        }
        if (tg != 0) { ceSum = 0.f; cntSum = 0; }   // one contribution per pixel

        // deterministic warp butterfly reduction -> per-chunk partial
        #pragma unroll
        for (int off = 16; off > 0; off >>= 1) {
            ceSum  += __shfl_xor_sync(0xffffffffu, ceSum, off);
            cntSum += __shfl_xor_sync(0xffffffffu, cntSum, off);
        }
        if (lane == 0) {
            g_blockCe[ck]  = ceSum;
            g_blockCnt[ck] = cntSum;
        }

        ck = nk;
    }

    // ---- fused finalize: last CTA reduces all per-chunk partials
    __shared__ bool isLast;
    __shared__ float sfw[NWARP];
    __shared__ int   siw[NWARP];
    __threadfence();
    __syncthreads();
    if (tid == 0) {
        unsigned int o = atomicAdd(&g_done, 1u);
        isLast = (o == (unsigned int)(gridDim.x - 1));
    }
    __syncthreads();
    if (isLast) {
        __threadfence();
        float s = 0.f; int c = 0;
        for (int i = tid; i < nchunks; i += TPB) {
            s += g_blockCe[i];
            c += g_blockCnt[i];
        }
        #pragma unroll
        for (int off = 16; off > 0; off >>= 1) {
            s += __shfl_xor_sync(0xffffffffu, s, off);
            c += __shfl_xor_sync(0xffffffffu, c, off);
        }
        if (lane == 0) { sfw[w] = s; siw[w] = c; }
        __syncthreads();
        if (tid == 0) {
            float tot = 0.f; int cnt = 0;
            #pragma unroll
            for (int i = 0; i < NWARP; i++) { tot += sfw[i]; cnt += siw[i]; }
            out[0] = tot / fmaxf((float)cnt, 1.0f);
        }
    }
}

// ---------------- launch ----------------
extern "C" void kernel_launch(void* const* d_in, const int* in_sizes, int n_in,
                              void* d_out, int out_size) {
    const float* feat = (const float*)d_in[0];
    const int*   mask = (const int*)d_in[1];
    const float* mean = (const float*)d_in[2];
    const float* cov  = (const float*)d_in[3];
    const float* tmem = (const float*)d_in[4];
    const float* ct   = (const float*)d_in[5];
    const float* cs   = (const float*)d_in[6];

    const int B = in_sizes[0] / (AF * HF * WF);
    const int npix = B * HF * WF;
    const int nchunks = npix / 32;

    cudaFuncSetAttribute(main_kernel,
                         cudaFuncAttributeMaxDynamicSharedMemorySize, SMEM_TOTAL);

    prep_kernel<<<KCOMP + NCLS + 1, 64>>>(cov, mean, tmem, ct, cs);
    main_kernel<<<148, TPB, SMEM_TOTAL>>>(feat, mask, (float*)d_out, nchunks);
}